// round 1
// baseline (speedup 1.0000x reference)
#include <cuda_runtime.h>
#include <math.h>

#define MM 16          // antennas
#define SS 8           // streams
#define KK 4           // bits/symbol
#define PP 16          // constellation points
#define WPB 4          // warps (batches) per block
#define EPS_ 1e-4f

struct WarpSmem {
    float2 S[16][17];     // covariance -> Cholesky L (in place)
    float2 Hw[16][8];     // h -> whitened h (in place)
    float2 yw[16];        // y -> whitened y
    float2 g[8][8];       // Gram = h^H h
    float2 ymf[8];        // matched filter h^H y
    float2 ymp[8][8];     // y_mf_pic [i][j]
    float2 gx[8];         // g @ x_hat
    float  ainv[16][17];  // inverse of a
    float  logits[8][16]; // per-point log priors (cached for demap)
    float  xr[8], xi[8], varx[8], rho[8];
    float  llr_a[8][4], llr_d[8][4];
};

__device__ __forceinline__ float pt_re(int p) {
    int b0 = (p >> 3) & 1, b2 = (p >> 1) & 1;
    return (float)((1 - 2 * b0) * (1 + 2 * b2)) * 0.31622776601683794f;
}
__device__ __forceinline__ float pt_im(int p) {
    int b1 = (p >> 2) & 1, b3 = p & 1;
    return (float)((1 - 2 * b1) * (1 + 2 * b3)) * 0.31622776601683794f;
}
__device__ __forceinline__ float logsig(float x) {
    // log(sigmoid(x)) = min(x,0) - log1p(exp(-|x|))
    return fminf(x, 0.f) - log1pf(__expf(-fabsf(x)));
}
// gr (real 16x16 rep of Gram) from complex g: [[Re,-Im],[Im,Re]]
__device__ __forceinline__ float gr_val(const WarpSmem& w, int i, int j) {
    float2 gij = w.g[i & 7][j & 7];
    float v;
    if (i < 8) v = (j < 8) ? gij.x : -gij.y;
    else       v = (j < 8) ? gij.y :  gij.x;
    return v;
}

__global__ __launch_bounds__(128)
void mmse_pic_kernel(const float* __restrict__ y_re, const float* __restrict__ y_im,
                     const float* __restrict__ h_re, const float* __restrict__ h_im,
                     const float* __restrict__ prior,
                     const float* __restrict__ s_re, const float* __restrict__ s_im,
                     float* __restrict__ out, int nbatch)
{
    const int warp = threadIdx.x >> 5;
    const int lane = threadIdx.x & 31;
    const int b = blockIdx.x * WPB + warp;
    const unsigned FULL = 0xffffffffu;

    __shared__ WarpSmem ws[WPB];
    if (b >= nbatch) return;
    WarpSmem& w = ws[warp];

    // ---------------- load inputs ----------------
    {
        const float* sre = s_re + (size_t)b * MM * MM;
        const float* sim = s_im + (size_t)b * MM * MM;
        #pragma unroll
        for (int t = lane; t < 256; t += 32) {
            int i = t >> 4, j = t & 15;
            w.S[i][j] = make_float2(sre[t], sim[t]);
        }
        const float* hre = h_re + (size_t)b * MM * SS;
        const float* him = h_im + (size_t)b * MM * SS;
        #pragma unroll
        for (int t = lane; t < 128; t += 32) {
            int m = t >> 3, s = t & 7;
            w.Hw[m][s] = make_float2(hre[t], him[t]);
        }
        if (lane < 16)
            w.yw[lane] = make_float2(y_re[(size_t)b * MM + lane], y_im[(size_t)b * MM + lane]);
        // prior -> llr_a  (32 values)
        w.llr_a[lane >> 2][lane & 3] = prior[(size_t)b * SS * KK + lane];
    }
    __syncwarp();

    // ---------------- Cholesky of S (complex, lower, in place) ----------------
    for (int k = 0; k < 16; ++k) {
        if (lane == 0) {
            float d = sqrtf(w.S[k][k].x);
            w.S[k][k] = make_float2(d, 0.f);
        }
        __syncwarp();
        const float invd = 1.0f / w.S[k][k].x;
        const int n = 15 - k;
        if (lane < n) {
            int j = k + 1 + lane;
            float2 v = w.S[j][k];
            w.S[j][k] = make_float2(v.x * invd, v.y * invd);
        }
        __syncwarp();
        // trailing Hermitian update over full (n x n) block: S[i][j] -= L[i][k]*conj(L[j][k])
        for (int t = lane; t < n * n; t += 32) {
            int i = k + 1 + t / n;
            int j = k + 1 + t % n;
            float2 a = w.S[i][k];
            float2 c = w.S[j][k];
            float2 sij = w.S[i][j];
            sij.x -= a.x * c.x + a.y * c.y;
            sij.y -= a.y * c.x - a.x * c.y;
            w.S[i][j] = sij;
        }
        __syncwarp();
    }

    // ---------------- forward substitution: L x = [y | h cols] (9 RHS) ----------------
    if (lane < 9) {
        float2 x[16];
        #pragma unroll
        for (int m = 0; m < 16; ++m)
            x[m] = (lane == 0) ? w.yw[m] : w.Hw[m][lane - 1];
        #pragma unroll
        for (int k = 0; k < 16; ++k) {
            float invd = 1.0f / w.S[k][k].x;
            float2 xk = make_float2(x[k].x * invd, x[k].y * invd);
            x[k] = xk;
            #pragma unroll
            for (int j = k + 1; j < 16; ++j) {
                float2 l = w.S[j][k];   // broadcast LDS across the 9 lanes
                x[j].x -= l.x * xk.x - l.y * xk.y;
                x[j].y -= l.x * xk.y + l.y * xk.x;
            }
        }
        #pragma unroll
        for (int m = 0; m < 16; ++m) {
            if (lane == 0) w.yw[m] = x[m];
            else           w.Hw[m][lane - 1] = x[m];
        }
    }
    __syncwarp();

    // ---------------- Gram g = h^H h  and  y_mf = h^H y ----------------
    #pragma unroll
    for (int t = lane; t < 64; t += 32) {
        int i = t >> 3, j = t & 7;
        float re = 0.f, im = 0.f;
        #pragma unroll
        for (int m = 0; m < 16; ++m) {
            float2 a = w.Hw[m][i], c = w.Hw[m][j];
            re += a.x * c.x + a.y * c.y;
            im += a.x * c.y - a.y * c.x;
        }
        w.g[i][j] = make_float2(re, im);
    }
    if (lane < 8) {
        float re = 0.f, im = 0.f;
        #pragma unroll
        for (int m = 0; m < 16; ++m) {
            float2 a = w.Hw[m][lane]; float2 yy = w.yw[m];
            re += a.x * yy.x + a.y * yy.y;
            im += a.x * yy.y - a.y * yy.x;
        }
        w.ymf[lane] = make_float2(re, im);
    }
    __syncwarp();

    // ---------------- MMSE-PIC iterations ----------------
    #pragma unroll 1
    for (int iter = 0; iter < 2; ++iter) {
        // (a) soft symbols: logits, mean, variance. lane = stream (0..7)
        if (lane < 8) {
            float l0 = w.llr_a[lane][0], l1 = w.llr_a[lane][1];
            float l2 = w.llr_a[lane][2], l3 = w.llr_a[lane][3];
            float lg[16];
            float mx = -1e30f;
            #pragma unroll
            for (int p = 0; p < 16; ++p) {
                float v = logsig(((p >> 3) & 1) ? l0 : -l0)
                        + logsig(((p >> 2) & 1) ? l1 : -l1)
                        + logsig(((p >> 1) & 1) ? l2 : -l2)
                        + logsig((p & 1) ? l3 : -l3);
                lg[p] = v;
                w.logits[lane][p] = v;
                mx = fmaxf(mx, v);
            }
            float se = 0.f, mre = 0.f, mim = 0.f, e2 = 0.f;
            #pragma unroll
            for (int p = 0; p < 16; ++p) {
                float e = __expf(lg[p] - mx);
                float pr = pt_re(p), pi = pt_im(p);
                se += e;
                mre += e * pr; mim += e * pi;
                e2 += e * (pr * pr + pi * pi);
            }
            float inv = 1.0f / se;
            mre *= inv; mim *= inv; e2 *= inv;
            w.xr[lane] = mre; w.xi[lane] = mim;
            w.varx[lane] = e2 - (mre * mre + mim * mim);
        }
        __syncwarp();

        // (b) gx = g @ x_hat, then y_mf_pic[i][j] = ymf[i] + g[i][j]*x[j] - gx[i]
        if (lane < 8) {
            float re = 0.f, im = 0.f;
            #pragma unroll
            for (int j = 0; j < 8; ++j) {
                float2 gij = w.g[lane][j];
                float xrj = w.xr[j], xij = w.xi[j];
                re += gij.x * xrj - gij.y * xij;
                im += gij.x * xij + gij.y * xrj;
            }
            w.gx[lane] = make_float2(re, im);
        }
        __syncwarp();
        #pragma unroll
        for (int t = lane; t < 64; t += 32) {
            int i = t >> 3, j = t & 7;
            float2 gij = w.g[i][j];
            float xrj = w.xr[j], xij = w.xi[j];
            float2 v = w.ymf[i];
            float2 gxi = w.gx[i];
            v.x += gij.x * xrj - gij.y * xij - gxi.x;
            v.y += gij.x * xij + gij.y * xrj - gxi.y;
            w.ymp[i][j] = v;
        }
        __syncwarp();

        // (c,d) a = gr*diag(var2) + I ; invert via Gauss-Jordan, lane = column of [a | I]
        float acol[16];
        {
            float vc = (lane < 16) ? w.varx[lane & 7] : 0.f;
            #pragma unroll
            for (int i = 0; i < 16; ++i) {
                if (lane < 16)
                    acol[i] = gr_val(w, i, lane) * vc + ((i == lane) ? 1.f : 0.f);
                else
                    acol[i] = (i == lane - 16) ? 1.f : 0.f;
            }
        }
        #pragma unroll
        for (int k = 0; k < 16; ++k) {
            float pivot = __shfl_sync(FULL, acol[k], k);
            float rowk = acol[k] * (1.0f / pivot);
            acol[k] = rowk;
            #pragma unroll
            for (int i = 0; i < 16; ++i) {
                if (i == k) continue;
                float f = __shfl_sync(FULL, acol[i], k);
                acol[i] -= f * rowk;
            }
        }
        if (lane >= 16) {
            #pragma unroll
            for (int i = 0; i < 16; ++i) w.ainv[i][lane - 16] = acol[i];
        }
        __syncwarp();

        // (e) mu = diag(ainv @ gr) (gr symmetric), z = rowsum(ainv * ypt_r)/mu
        if (lane < 16) {
            const int i = lane;
            const int s = i & 7;
            float mu = 0.f, zz = 0.f;
            #pragma unroll
            for (int j = 0; j < 16; ++j) {
                float av = w.ainv[i][j];
                mu += av * gr_val(w, j, i);
                float2 yv = w.ymp[j & 7][s];
                zz += av * ((j < 8) ? yv.x : yv.y);
            }
            zz /= mu;
            if (i < 8) {
                w.xr[i] = zz;
                w.rho[i] = mu / fmaxf(1.f - w.varx[i] * mu, EPS_);
            } else {
                w.xi[i - 8] = zz;
            }
        }
        __syncwarp();

        // (f) max-log demap with prior logits
        if (lane < 8) {
            const int s = lane;
            float xrv = w.xr[s], xiv = w.xi[s];
            float rho = w.rho[s];
            float m1[4], m0[4];
            #pragma unroll
            for (int q = 0; q < 4; ++q) { m1[q] = -1e30f; m0[q] = -1e30f; }
            #pragma unroll
            for (int p = 0; p < 16; ++p) {
                float dr = xrv - pt_re(p), di = xiv - pt_im(p);
                float e = -(dr * dr + di * di) * rho + w.logits[s][p];
                #pragma unroll
                for (int q = 0; q < 4; ++q) {
                    if ((p >> (3 - q)) & 1) m1[q] = fmaxf(m1[q], e);
                    else                    m0[q] = fmaxf(m0[q], e);
                }
            }
            #pragma unroll
            for (int q = 0; q < 4; ++q) w.llr_d[s][q] = m1[q] - m0[q];
        }
        __syncwarp();

        if (iter == 0) {
            // llr_a <- llr_d for next iteration
            w.llr_a[lane >> 2][lane & 3] = w.llr_d[lane >> 2][lane & 3];
            __syncwarp();
        }
    }

    // ---------------- output: extrinsic LLR = llr_d - llr_a ----------------
    out[(size_t)b * SS * KK + lane] =
        w.llr_d[lane >> 2][lane & 3] - w.llr_a[lane >> 2][lane & 3];
}

extern "C" void kernel_launch(void* const* d_in, const int* in_sizes, int n_in,
                              void* d_out, int out_size)
{
    const float* y_re  = (const float*)d_in[0];
    const float* y_im  = (const float*)d_in[1];
    const float* h_re  = (const float*)d_in[2];
    const float* h_im  = (const float*)d_in[3];
    const float* prior = (const float*)d_in[4];
    const float* s_re  = (const float*)d_in[5];
    const float* s_im  = (const float*)d_in[6];
    float* out = (float*)d_out;

    int nbatch = in_sizes[0] / MM;   // y_re is [B, M]
    int blocks = (nbatch + WPB - 1) / WPB;
    mmse_pic_kernel<<<blocks, WPB * 32>>>(y_re, y_im, h_re, h_im, prior,
                                          s_re, s_im, out, nbatch);
}

// round 2
// speedup vs baseline: 2.5956x; 2.5956x over previous
#include <cuda_runtime.h>
#include <math.h>

#define WPB 4
#define FULL 0xffffffffu
#define INVS10 0.31622776601683794f   // 1/sqrt(10)
#define EPS_ 1e-4f

struct ItSmem {
    float2 g[8][9];   // g[i][j] Gram; column 8 = ymf (matched filter)
    float2 u[8];      // ymf - g*x
    float2 Mc[8];     // (W g)[s][s]
    float2 Wu[8];     // (W u)[s]
};

struct WarpSmem {
    union {
        struct { float Ar[16][25]; float Ai[16][25]; } ld;  // [S | H | y] staging
        ItSmem it;
    } a;
    float2 HY[16][9]; // whitened [H | y]
};

__global__ __launch_bounds__(128)
void mmse_pic_kernel(const float* __restrict__ y_re, const float* __restrict__ y_im,
                     const float* __restrict__ h_re, const float* __restrict__ h_im,
                     const float* __restrict__ prior,
                     const float* __restrict__ s_re, const float* __restrict__ s_im,
                     float* __restrict__ out, int nbatch)
{
    const int warp = threadIdx.x >> 5;
    const int lane = threadIdx.x & 31;
    const int b = blockIdx.x * WPB + warp;

    __shared__ WarpSmem ws[WPB];
    if (b >= nbatch) return;
    WarpSmem& w = ws[warp];

    // ---------------- stage inputs (coalesced) into A = [S | H | y] ----------------
    {
        const float* sre = s_re + (size_t)b * 256;
        const float* sim = s_im + (size_t)b * 256;
        #pragma unroll
        for (int t = lane; t < 256; t += 32) {
            w.a.ld.Ar[t >> 4][t & 15] = sre[t];
            w.a.ld.Ai[t >> 4][t & 15] = sim[t];
        }
        const float* hre = h_re + (size_t)b * 128;
        const float* him = h_im + (size_t)b * 128;
        #pragma unroll
        for (int t = lane; t < 128; t += 32) {
            w.a.ld.Ar[t >> 3][16 + (t & 7)] = hre[t];
            w.a.ld.Ai[t >> 3][16 + (t & 7)] = him[t];
        }
        if (lane < 16) {
            w.a.ld.Ar[lane][24] = y_re[(size_t)b * 16 + lane];
            w.a.ld.Ai[lane][24] = y_im[(size_t)b * 16 + lane];
        }
    }
    // prior LLRs: lane s<8 keeps its 4 bits in registers
    float l0 = 0.f, l1 = 0.f, l2 = 0.f, l3 = 0.f;
    if (lane < 8) {
        float4 p = *(const float4*)(prior + (size_t)b * 32 + lane * 4);
        l0 = p.x; l1 = p.y; l2 = p.z; l3 = p.w;
    }
    __syncwarp();

    // ---------------- column-per-lane registers for forward elimination ----------------
    float ar[16], ai[16];
    {
        int c = (lane < 25) ? lane : 24;  // idle lanes mirror y column (harmless)
        #pragma unroll
        for (int m = 0; m < 16; m++) { ar[m] = w.a.ld.Ar[m][c]; ai[m] = w.a.ld.Ai[m][c]; }
    }
    __syncwarp();   // Ar/Ai dead after this point (aliased by ItSmem later)

    // ---------------- forward Gaussian elimination on [S | H | y] ----------------
    // S = L D L^H ; pivots d_k real > 0. Afterwards RHS rows scaled by rsqrt(d_k)
    // give the Cholesky-whitened [Hw | yw] = C^{-1}[H|y], C = L D^{1/2}.
    #pragma unroll
    for (int k = 0; k < 16; k++) {
        float dk = __shfl_sync(FULL, ar[k], k);
        float invd = __fdividef(1.0f, dk);
        float rsd = rsqrtf(dk);
        #pragma unroll
        for (int i = k + 1; i < 16; i++) {
            float mr = __shfl_sync(FULL, ar[i], k) * invd;
            float mi = __shfl_sync(FULL, ai[i], k) * invd;
            ar[i] = fmaf(-mr, ar[k], fmaf( mi, ai[k], ar[i]));
            ai[i] = fmaf(-mr, ai[k], fmaf(-mi, ar[k], ai[i]));
        }
        ar[k] *= rsd; ai[k] *= rsd;   // row-k final after this step
    }

    // write whitened [H | y] columns
    if (lane >= 16 && lane < 25) {
        int j = lane - 16;
        #pragma unroll
        for (int m = 0; m < 16; m++) w.HY[m][j] = make_float2(ar[m], ai[m]);
    }
    __syncwarp();

    // ---------------- Gram g = Hw^H Hw (8x8) and ymf = Hw^H yw (column 8) ----------------
    #pragma unroll
    for (int r = 0; r < 3; r++) {
        int t = lane + 32 * r;
        if (t < 72) {
            int i = t / 9, j = t - 9 * i;
            float re = 0.f, im = 0.f;
            #pragma unroll
            for (int m = 0; m < 16; m++) {
                float2 a2 = w.HY[m][i], c2 = w.HY[m][j];
                re = fmaf(a2.x, c2.x, fmaf(a2.y, c2.y, re));
                im = fmaf(a2.x, c2.y, fmaf(-a2.y, c2.x, im));
            }
            w.a.it.g[i][j] = make_float2(re, im);
        }
    }
    __syncwarp();

    // ---------------- MMSE-PIC iterations ----------------
    float d0 = 0.f, d1 = 0.f, d2 = 0.f, d3 = 0.f;       // llr_d
    float pa0 = 0.f, pa1 = 0.f, pa2 = 0.f, pa3 = 0.f;   // llr_a (final iter)

    #pragma unroll 1
    for (int iter = 0; iter < 2; iter++) {
        // (a) soft-symbol moments via per-bit factorization (4 sigmoids, no softmax)
        float s0 = __fdividef(1.f, 1.f + __expf(-l0));
        float s1 = __fdividef(1.f, 1.f + __expf(-l1));
        float s2 = __fdividef(1.f, 1.f + __expf(-l2));
        float s3 = __fdividef(1.f, 1.f + __expf(-l3));
        float mre = (1.f - 2.f * s0) * (1.f + 2.f * s2) * INVS10;
        float mim = (1.f - 2.f * s1) * (1.f + 2.f * s3) * INVS10;
        float var = (2.f + 8.f * (s2 + s3)) * 0.1f - (mre * mre + mim * mim);

        // (b) u = ymf - g @ x_hat  (lanes 0..7; shfl within converged subset mask 0xff)
        if (lane < 8) {
            float2 acc = w.a.it.g[lane][8];   // ymf
            #pragma unroll
            for (int j = 0; j < 8; j++) {
                float xrj = __shfl_sync(0xffu, mre, j);
                float xij = __shfl_sync(0xffu, mim, j);
                float2 gij = w.a.it.g[lane][j];
                acc.x -= gij.x * xrj - gij.y * xij;
                acc.y -= gij.x * xij + gij.y * xrj;
            }
            w.a.it.u[lane] = acc;
        }
        __syncwarp();

        // (c) build augmented complex system: columns [a_c | g | u]
        //     a_c = I + g*diag(var)  (pivots real positive; no pivoting needed)
        float cr[8], ci[8];
        if (lane < 16) {
            int j = lane & 7;
            #pragma unroll
            for (int i = 0; i < 8; i++) {
                float2 gij = w.a.it.g[i][j];
                if (lane < 8) {
                    cr[i] = fmaf(gij.x, var, (i == j) ? 1.f : 0.f);
                    ci[i] = gij.y * var;
                } else {
                    cr[i] = gij.x; ci[i] = gij.y;
                }
            }
        } else if (lane == 16) {
            #pragma unroll
            for (int i = 0; i < 8; i++) { float2 uu = w.a.it.u[i]; cr[i] = uu.x; ci[i] = uu.y; }
        } else {
            #pragma unroll
            for (int i = 0; i < 8; i++) { cr[i] = 0.f; ci[i] = 0.f; }
        }

        // (d) 8x8 complex Gauss-Jordan; lanes 8..16 become [W g | W u], W = a_c^{-1}
        #pragma unroll
        for (int k = 0; k < 8; k++) {
            float dk = __shfl_sync(FULL, cr[k], k);     // pivot is real
            float invd = __fdividef(1.f, dk);
            cr[k] *= invd; ci[k] *= invd;
            #pragma unroll
            for (int i = 0; i < 8; i++) {
                if (i == k) continue;
                float mr = __shfl_sync(FULL, cr[i], k);
                float mi = __shfl_sync(FULL, ci[i], k);
                cr[i] = fmaf(-mr, cr[k], fmaf( mi, ci[k], cr[i]));
                ci[i] = fmaf(-mr, ci[k], fmaf(-mi, cr[k], ci[i]));
            }
        }

        // (e) extract Mc_s = (Wg)[s][s] (lane 8+s, reg s) and Wu (lane 16)
        if (lane >= 8 && lane < 16) {
            int s = lane - 8;
            float vr = 0.f, vi = 0.f;
            #pragma unroll
            for (int q = 0; q < 8; q++) if (q == s) { vr = cr[q]; vi = ci[q]; }
            w.a.it.Mc[s] = make_float2(vr, vi);
        }
        if (lane == 16) {
            #pragma unroll
            for (int s = 0; s < 8; s++) w.a.it.Wu[s] = make_float2(cr[s], ci[s]);
        }
        __syncwarp();

        // finalize + separable max-log demap (lane-local per stream)
        if (lane < 8) {
            float2 Mc = w.a.it.Mc[lane];
            float2 Wu = w.a.it.Wu[lane];
            float mu = Mc.x;
            // v = Wu + x_soft * Mc  (complex)
            float vr = Wu.x + mre * Mc.x - mim * Mc.y;
            float vi = Wu.y + mre * Mc.y + mim * Mc.x;
            float invmu = __fdividef(1.f, mu);
            float xr_ = vr * invmu, xi_ = vi * invmu;
            float rho = mu * __fdividef(1.f, fmaxf(1.f - var * mu, EPS_));

            float q1 = rho * 0.1f;              // rho * s^2
            float c1 = 2.f * INVS10 * rho * xr_;
            float RE00 =        c1 -       q1;
            float RE01 =  3.f * c1 - 9.f * q1 + l2;
            float RE10 =       -c1 -       q1 + l0;
            float RE11 = -3.f * c1 - 9.f * q1 + l0 + l2;
            d0 = fmaxf(RE10, RE11) - fmaxf(RE00, RE01);
            d2 = fmaxf(RE01, RE11) - fmaxf(RE00, RE10);
            float c2 = 2.f * INVS10 * rho * xi_;
            float IM00 =        c2 -       q1;
            float IM01 =  3.f * c2 - 9.f * q1 + l3;
            float IM10 =       -c2 -       q1 + l1;
            float IM11 = -3.f * c2 - 9.f * q1 + l1 + l3;
            d1 = fmaxf(IM10, IM11) - fmaxf(IM00, IM01);
            d3 = fmaxf(IM01, IM11) - fmaxf(IM00, IM10);
        }

        if (iter == 0) {
            pa0 = d0; pa1 = d1; pa2 = d2; pa3 = d3;
            l0 = d0; l1 = d1; l2 = d2; l3 = d3;   // llr_a <- llr_d
        }
    }

    // ---------------- extrinsic output ----------------
    if (lane < 8) {
        float4 o = make_float4(d0 - pa0, d1 - pa1, d2 - pa2, d3 - pa3);
        *(float4*)(out + (size_t)b * 32 + lane * 4) = o;
    }
}

extern "C" void kernel_launch(void* const* d_in, const int* in_sizes, int n_in,
                              void* d_out, int out_size)
{
    const float* y_re  = (const float*)d_in[0];
    const float* y_im  = (const float*)d_in[1];
    const float* h_re  = (const float*)d_in[2];
    const float* h_im  = (const float*)d_in[3];
    const float* prior = (const float*)d_in[4];
    const float* s_re  = (const float*)d_in[5];
    const float* s_im  = (const float*)d_in[6];
    float* out = (float*)d_out;

    int nbatch = in_sizes[0] / 16;   // y_re is [B, M]
    int blocks = (nbatch + WPB - 1) / WPB;
    mmse_pic_kernel<<<blocks, WPB * 32>>>(y_re, y_im, h_re, h_im, prior,
                                          s_re, s_im, out, nbatch);
}